// round 7
// baseline (speedup 1.0000x reference)
#include <cuda_runtime.h>
#include <math.h>
#include <stdint.h>

// ---------------- problem constants ----------------
#define Bb 64
#define Nn 300
#define Cc 256
#define Hh 8
#define HD 32
#define BH (Bb*Hh)          // 512
#define ROWS (Bb*Nn)        // 19200
#define QR 8                // queries per warp (register-blocked)
#define AW 16               // warps in attention CTA
#define KP2 33              // u64 pitch for dup-K rows (conflict-free)

// ---------------- scratch (device globals; no runtime alloc) ----------------
__device__ float g_q[BH * Nn * HD];     // [b,h,n,d]
__device__ float g_k[BH * Nn * HD];
__device__ float g_v[BH * Nn * HD];
__device__ float g_posmx[Hh * Nn];      // per-(h,n) positional logit max
__device__ float g_posinv[Hh * Nn];     // g(h) / sum(exp(logit - max))
__device__ float g_oh[ROWS * Cc];       // attention output, [b,n,h*32+d]
__device__ __align__(16) float g_at[(size_t)BH * AW * QR * Nn];  // attn rows (L2)

// ---------------- packed f32x2 helpers ----------------
__device__ __forceinline__ unsigned long long pk2(float x, float y) {
    unsigned long long r;
    asm("mov.b64 %0, {%1,%2};" : "=l"(r)
        : "r"(__float_as_uint(x)), "r"(__float_as_uint(y)));
    return r;
}
__device__ __forceinline__ void fma2(unsigned long long& d,
                                     unsigned long long a, unsigned long long b) {
    asm("fma.rn.f32x2 %0, %1, %2, %0;" : "+l"(d) : "l"(a), "l"(b));
}
__device__ __forceinline__ void upk2(float& lo, float& hi, unsigned long long v) {
    uint32_t l, h;
    asm("mov.b64 {%0,%1}, %2;" : "=r"(l), "=r"(h) : "l"(v));
    lo = __uint_as_float(l); hi = __uint_as_float(h);
}

// =====================================================================
// positional softmax stats: logit[h][n][m] = w0*d + w2*d^2 + b, d = m-n.
// =====================================================================
__global__ void pos_kernel(const float* __restrict__ Wpos,
                           const float* __restrict__ bpos,
                           const float* __restrict__ gating)
{
    int row  = blockIdx.x * 4 + (threadIdx.x >> 5);   // h*300 + n
    int lane = threadIdx.x & 31;
    if (row >= Hh * Nn) return;
    int h = row / Nn, n = row % Nn;
    float w0 = Wpos[h*3+0], w2 = Wpos[h*3+2], b = bpos[h];

    float s[10], mx = -1e30f;
    #pragma unroll
    for (int t = 0; t < 10; t++) {
        int m = t*32 + lane;
        float v = -1e30f;
        if (m < Nn) { float d = (float)(m - n); v = fmaf(w2*d, d, fmaf(w0, d, b)); }
        s[t] = v; mx = fmaxf(mx, v);
    }
    #pragma unroll
    for (int o = 16; o; o >>= 1) mx = fmaxf(mx, __shfl_xor_sync(0xffffffffu, mx, o));
    float esum = 0.f;
    #pragma unroll
    for (int t = 0; t < 10; t++) esum += __expf(s[t] - mx);
    #pragma unroll
    for (int o = 16; o; o >>= 1) esum += __shfl_xor_sync(0xffffffffu, esum, o);
    if (lane == 0) {
        float g = 1.0f / (1.0f + __expf(-gating[h]));
        g_posmx[row]  = mx;
        g_posinv[row] = g / esum;
    }
}

// =====================================================================
// GEMM: out[M,Ncols] = A[M,256] @ W[Ncols,256]^T  (FFMA2 over col-pairs)
// =====================================================================
#define KT 16
__global__ __launch_bounds__(256, 2)
void gemm_kernel(const float* __restrict__ A,
                 const float* __restrict__ W0,
                 const float* __restrict__ W1,
                 const float* __restrict__ bias,
                 float* __restrict__ out,
                 int mode)
{
    __shared__ __align__(16) float As[2][KT][132];
    __shared__ __align__(16) float Bs[2][KT][132];

    int tid  = threadIdx.x;
    int row0 = blockIdx.y * 128;
    int col0 = blockIdx.x * 128;
    int tx = tid & 15, ty = tid >> 4;

    const float* Ap = (mode == 0) ? A : g_oh;

    int lr = tid >> 1;
    int lk = (tid & 1) * 8;
    const float* arow = Ap + (size_t)(row0 + lr) * 256 + lk;
    int c = col0 + lr;
    const float* wrow;
    if (mode == 0) wrow = (c < 512) ? (W0 + (size_t)c * 256 + lk)
                                    : (W1 + (size_t)(c - 512) * 256 + lk);
    else           wrow = W0 + (size_t)c * 256 + lk;

    unsigned long long acc2[8][4];
    #pragma unroll
    for (int i = 0; i < 8; i++)
        #pragma unroll
        for (int jp = 0; jp < 4; jp++) acc2[i][jp] = 0ULL;

    float4 ra0, ra1, rb0, rb1;
    ra0 = *(const float4*)(arow + 0);
    ra1 = *(const float4*)(arow + 4);
    rb0 = *(const float4*)(wrow + 0);
    rb1 = *(const float4*)(wrow + 4);
    int buf = 0;
    {
        As[0][lk+0][lr]=ra0.x; As[0][lk+1][lr]=ra0.y; As[0][lk+2][lr]=ra0.z; As[0][lk+3][lr]=ra0.w;
        As[0][lk+4][lr]=ra1.x; As[0][lk+5][lr]=ra1.y; As[0][lk+6][lr]=ra1.z; As[0][lk+7][lr]=ra1.w;
        Bs[0][lk+0][lr]=rb0.x; Bs[0][lk+1][lr]=rb0.y; Bs[0][lk+2][lr]=rb0.z; Bs[0][lk+3][lr]=rb0.w;
        Bs[0][lk+4][lr]=rb1.x; Bs[0][lk+5][lr]=rb1.y; Bs[0][lk+6][lr]=rb1.z; Bs[0][lk+7][lr]=rb1.w;
    }
    __syncthreads();

    for (int k0 = 0; k0 < 256; k0 += KT) {
        bool has_next = (k0 + KT) < 256;
        if (has_next) {
            ra0 = *(const float4*)(arow + k0 + KT + 0);
            ra1 = *(const float4*)(arow + k0 + KT + 4);
            rb0 = *(const float4*)(wrow + k0 + KT + 0);
            rb1 = *(const float4*)(wrow + k0 + KT + 4);
        }
        #pragma unroll
        for (int kk = 0; kk < KT; kk++) {
            float4 a0 = *(const float4*)&As[buf][kk][ty*4];
            float4 a1 = *(const float4*)&As[buf][kk][64 + ty*4];
            ulonglong2 bb0 = *(const ulonglong2*)&Bs[buf][kk][tx*4];
            ulonglong2 bb1 = *(const ulonglong2*)&Bs[buf][kk][64 + tx*4];
            unsigned long long bp[4] = {bb0.x, bb0.y, bb1.x, bb1.y};
            float a[8] = {a0.x,a0.y,a0.z,a0.w, a1.x,a1.y,a1.z,a1.w};
            #pragma unroll
            for (int i = 0; i < 8; i++) {
                unsigned long long ap = pk2(a[i], a[i]);
                #pragma unroll
                for (int jp = 0; jp < 4; jp++)
                    fma2(acc2[i][jp], ap, bp[jp]);
            }
        }
        if (has_next) {
            int nb = buf ^ 1;
            As[nb][lk+0][lr]=ra0.x; As[nb][lk+1][lr]=ra0.y; As[nb][lk+2][lr]=ra0.z; As[nb][lk+3][lr]=ra0.w;
            As[nb][lk+4][lr]=ra1.x; As[nb][lk+5][lr]=ra1.y; As[nb][lk+6][lr]=ra1.z; As[nb][lk+7][lr]=ra1.w;
            Bs[nb][lk+0][lr]=rb0.x; Bs[nb][lk+1][lr]=rb0.y; Bs[nb][lk+2][lr]=rb0.z; Bs[nb][lk+3][lr]=rb0.w;
            Bs[nb][lk+4][lr]=rb1.x; Bs[nb][lk+5][lr]=rb1.y; Bs[nb][lk+6][lr]=rb1.z; Bs[nb][lk+7][lr]=rb1.w;
            __syncthreads();
            buf = nb;
        }
    }

    #pragma unroll
    for (int i = 0; i < 8; i++) {
        int r = row0 + ((i < 4) ? (ty*4 + i) : (64 + ty*4 + i - 4));
        int bidx = r / Nn, n = r % Nn;
        #pragma unroll
        for (int jp = 0; jp < 4; jp++) {
            int col = col0 + ((jp < 2) ? (tx*4 + jp*2) : (64 + tx*4 + (jp-2)*2));
            float d0, d1; upk2(d0, d1, acc2[i][jp]);
            if (mode == 0) {
                int d = col & 31;
                if (col < 512) {
                    int h = (col >> 5) & 7;
                    float* dst = (col < 256) ? g_q : g_k;
                    *(float2*)(dst + (((size_t)bidx*Hh + h)*Nn + n)*HD + d) = make_float2(d0, d1);
                } else {
                    int h = (col - 512) >> 5;
                    *(float2*)(g_v + (((size_t)bidx*Hh + h)*Nn + n)*HD + d) = make_float2(d0, d1);
                }
            } else {
                *(float2*)(out + (size_t)r * 256 + col) =
                    make_float2(d0 + bias[col], d1 + bias[col + 1]);
            }
        }
    }
}

// =====================================================================
// Attention: one CTA per (b,h), 16 warps, QR=8.
// smem: K pre-duplicated as (k,k) u64 (no packs in QK), V pre-paired
// over adjacent m (no packs in AV). attn rows spill to gmem (L2).
// attn = (1-g)*softmax(QK^T*scale) + g*pos  (rows sum to 1 -> no renorm)
// =====================================================================
#define SM_U64_KS2 (Nn*KP2)          // 9900 u64
#define SM_U64_VS2 ((Nn/2)*32)       // 4800 u64
#define SMEM_ATTN_BYTES ((SM_U64_KS2 + SM_U64_VS2)*8 + AW*QR*HD*4)  // ~134 KB

__global__ __launch_bounds__(AW*32)
void attn_kernel(const float* __restrict__ Wpos,
                 const float* __restrict__ bpos,
                 const float* __restrict__ gating)
{
    extern __shared__ __align__(16) unsigned long long smu[];
    unsigned long long* ks2 = smu;                     // [m*KP2 + d] = (k,k)
    unsigned long long* vs2 = smu + SM_U64_KS2;        // [(m/2)*32 + d] = (V[m],V[m+1])
    float* qs = (float*)(smu + SM_U64_KS2 + SM_U64_VS2);

    int bh = blockIdx.x;               // b*8 + h
    int h  = bh & 7, bidx = bh >> 3;
    int tid = threadIdx.x, wid = tid >> 5, lane = tid & 31;

    const float* kg = g_k + (size_t)bh * Nn * HD;
    const float* vg = g_v + (size_t)bh * Nn * HD;
    const float* qg = g_q + (size_t)bh * Nn * HD;

    // stage K duplicated pairs
    for (int i = tid; i < Nn * 8; i += AW*32) {
        int m = i >> 3, d = (i & 7) * 4;
        float4 kv4 = *(const float4*)(kg + m*HD + d);
        ks2[m*KP2 + d + 0] = pk2(kv4.x, kv4.x);
        ks2[m*KP2 + d + 1] = pk2(kv4.y, kv4.y);
        ks2[m*KP2 + d + 2] = pk2(kv4.z, kv4.z);
        ks2[m*KP2 + d + 3] = pk2(kv4.w, kv4.w);
    }
    // stage V paired over adjacent m
    for (int i = tid; i < (Nn/2) * 8; i += AW*32) {
        int mp = i >> 3, d = (i & 7) * 4;
        float4 va = *(const float4*)(vg + (2*mp)*HD + d);
        float4 vb = *(const float4*)(vg + (2*mp+1)*HD + d);
        vs2[mp*32 + d + 0] = pk2(va.x, vb.x);
        vs2[mp*32 + d + 1] = pk2(va.y, vb.y);
        vs2[mp*32 + d + 2] = pk2(va.z, vb.z);
        vs2[mp*32 + d + 3] = pk2(va.w, vb.w);
    }
    __syncthreads();

    float g  = 1.0f / (1.0f + __expf(-gating[h]));
    float w0 = Wpos[h*3+0], w2 = Wpos[h*3+2], bps = bpos[h];
    const float scale = 0.17677669529663687f;   // 1/sqrt(32)
    float* myq  = qs + wid * (QR*HD);
    float* myat = g_at + ((size_t)bh * AW + wid) * (QR*Nn);

    for (int n0 = wid*QR; n0 < Nn; n0 += AW*QR) {
        // stage q interleaved: myq[d*QR + qq]
        #pragma unroll
        for (int qq = 0; qq < QR; qq++) {
            int n = n0 + qq; int nc = (n < Nn) ? n : (Nn-1);
            myq[lane*QR + qq] = qg[nc*HD + lane];
        }
        __syncwarp();

        // ---- QK: acc2[p][t] = {score(2p), score(2p+1)} at m=t*32+lane ----
        unsigned long long acc2[4][10];
        #pragma unroll
        for (int p = 0; p < 4; p++)
            #pragma unroll
            for (int t = 0; t < 10; t++) acc2[p][t] = 0ULL;

        #pragma unroll
        for (int d = 0; d < HD; d++) {
            ulonglong2 qa = *(const ulonglong2*)&myq[d*QR];      // (q0,q1),(q2,q3)
            ulonglong2 qb = *(const ulonglong2*)&myq[d*QR + 4];  // (q4,q5),(q6,q7)
            #pragma unroll
            for (int t = 0; t < 10; t++) {
                unsigned long long kp = ks2[(t*32 + lane)*KP2 + d];
                fma2(acc2[0][t], qa.x, kp);
                fma2(acc2[1][t], qa.y, kp);
                fma2(acc2[2][t], qb.x, kp);
                fma2(acc2[3][t], qb.y, kp);
            }
        }

        // ---- softmax + gated mix per query; rows -> gmem (L2) ----
        #pragma unroll
        for (int p = 0; p < 4; p++) {
            #pragma unroll
            for (int half = 0; half < 2; half++) {
                int qq = p*2 + half;
                int n = n0 + qq; int nc = (n < Nn) ? n : (Nn-1);
                float s[10], mx = -1e30f;
                #pragma unroll
                for (int t = 0; t < 10; t++) {
                    float lo, hi; upk2(lo, hi, acc2[p][t]);
                    float v = half ? hi : lo;
                    int m = t*32 + lane;
                    v = (m < Nn) ? v * scale : -1e30f;
                    s[t] = v; mx = fmaxf(mx, v);
                }
                #pragma unroll
                for (int o = 16; o; o >>= 1) mx = fmaxf(mx, __shfl_xor_sync(0xffffffffu, mx, o));
                float esum = 0.f;
                #pragma unroll
                for (int t = 0; t < 10; t++) { s[t] = __expf(s[t] - mx); esum += s[t]; }
                #pragma unroll
                for (int o = 16; o; o >>= 1) esum += __shfl_xor_sync(0xffffffffu, esum, o);
                float inv  = (1.0f - g) / esum;
                float pmx  = g_posmx[h*Nn + nc];
                float pinv = g_posinv[h*Nn + nc];
                if (n < Nn) {
                    #pragma unroll
                    for (int t = 0; t < 10; t++) {
                        int m = t*32 + lane;
                        if (m < Nn) {
                            float dd = (float)(m - nc);
                            float pe = __expf(fmaf(w2*dd, dd, fmaf(w0, dd, bps)) - pmx) * pinv;
                            myat[qq*Nn + m] = fmaf(s[t], inv, pe);
                        }
                    }
                }
            }
        }
        __threadfence_block();
        __syncwarp();

        // ---- AV: o2[qq] = paired sums over m of attn*V[.,lane] ----
        unsigned long long o2[QR];
        #pragma unroll
        for (int qq = 0; qq < QR; qq++) o2[qq] = 0ULL;

        #pragma unroll 2
        for (int m0 = 0; m0 < Nn; m0 += 4) {
            unsigned long long vp01 = vs2[(m0 >> 1)*32 + lane];
            unsigned long long vp23 = vs2[((m0 >> 1) + 1)*32 + lane];
            #pragma unroll
            for (int qq = 0; qq < QR; qq++) {
                ulonglong2 a2 = *(const ulonglong2*)&myat[qq*Nn + m0];
                fma2(o2[qq], a2.x, vp01);
                fma2(o2[qq], a2.y, vp23);
            }
        }
        #pragma unroll
        for (int qq = 0; qq < QR; qq++) {
            int n = n0 + qq;
            if (n < Nn) {
                float lo, hi; upk2(lo, hi, o2[qq]);
                g_oh[((size_t)bidx*Nn + n)*Cc + h*HD + lane] = lo + hi;
            }
        }
        __syncwarp();
    }
}

// =====================================================================
extern "C" void kernel_launch(void* const* d_in, const int* in_sizes, int n_in,
                              void* d_out, int out_size)
{
    const float* x      = (const float*)d_in[0];
    const float* Wqk    = (const float*)d_in[1];
    const float* Wv     = (const float*)d_in[2];
    const float* Wpos   = (const float*)d_in[3];
    const float* bpos   = (const float*)d_in[4];
    const float* Wproj  = (const float*)d_in[5];
    const float* bproj  = (const float*)d_in[6];
    const float* gating = (const float*)d_in[7];
    float* out = (float*)d_out;

    cudaFuncSetAttribute(attn_kernel, cudaFuncAttributeMaxDynamicSharedMemorySize,
                         SMEM_ATTN_BYTES);

    // 1) positional softmax stats
    pos_kernel<<<(Hh*Nn + 3) / 4, 128>>>(Wpos, bpos, gating);

    // 2) QKV projection: [19200,256] @ [768,256]^T
    dim3 g1(6, ROWS / 128);
    gemm_kernel<<<g1, 256>>>(x, Wqk, Wv, nullptr, nullptr, 0);

    // 3) fused gated attention, one CTA per (b,h)
    attn_kernel<<<BH, AW*32, SMEM_ATTN_BYTES>>>(Wpos, bpos, gating);

    // 4) output projection + bias
    dim3 g2(2, ROWS / 128);
    gemm_kernel<<<g2, 256>>>(nullptr, Wproj, nullptr, bproj, out, 1);
}

// round 8
// speedup vs baseline: 1.1635x; 1.1635x over previous
#include <cuda_runtime.h>
#include <math.h>
#include <stdint.h>

// ---------------- problem constants ----------------
#define Bb 64
#define Nn 300
#define Cc 256
#define Hh 8
#define HD 32
#define BH (Bb*Hh)          // 512
#define ROWS (Bb*Nn)        // 19200
#define QR 4                // queries per warp (register-blocked)
#define AW 8                // warps in attention CTA (2 CTAs/SM)
#define KP 33               // float pitch for K rows (conflict-free)

// ---------------- scratch (device globals; no runtime alloc) ----------------
__device__ float g_q[BH * Nn * HD];     // [b,h,n,d]
__device__ float g_k[BH * Nn * HD];
__device__ float g_v[BH * Nn * HD];
__device__ float g_posmx[Hh * Nn];      // per-(h,n) positional logit max
__device__ float g_posinv[Hh * Nn];     // g(h) / sum(exp(logit - max))
__device__ float g_oh[ROWS * Cc];       // attention output, [b,n,h*32+d]

// ---------------- packed f32x2 helpers ----------------
__device__ __forceinline__ unsigned long long pk2(float x, float y) {
    unsigned long long r;
    asm("mov.b64 %0, {%1,%2};" : "=l"(r)
        : "r"(__float_as_uint(x)), "r"(__float_as_uint(y)));
    return r;
}
__device__ __forceinline__ void fma2(unsigned long long& d,
                                     unsigned long long a, unsigned long long b) {
    asm("fma.rn.f32x2 %0, %1, %2, %0;" : "+l"(d) : "l"(a), "l"(b));
}
__device__ __forceinline__ void upk2(float& lo, float& hi, unsigned long long v) {
    uint32_t l, h;
    asm("mov.b64 {%0,%1}, %2;" : "=r"(l), "=r"(h) : "l"(v));
    lo = __uint_as_float(l); hi = __uint_as_float(h);
}

// =====================================================================
// positional softmax stats: logit[h][n][m] = w0*d + w2*d^2 + b, d = m-n.
// =====================================================================
__global__ void pos_kernel(const float* __restrict__ Wpos,
                           const float* __restrict__ bpos,
                           const float* __restrict__ gating)
{
    int row  = blockIdx.x * 4 + (threadIdx.x >> 5);   // h*300 + n
    int lane = threadIdx.x & 31;
    if (row >= Hh * Nn) return;
    int h = row / Nn, n = row % Nn;
    float w0 = Wpos[h*3+0], w2 = Wpos[h*3+2], b = bpos[h];

    float s[10], mx = -1e30f;
    #pragma unroll
    for (int t = 0; t < 10; t++) {
        int m = t*32 + lane;
        float v = -1e30f;
        if (m < Nn) { float d = (float)(m - n); v = fmaf(w2*d, d, fmaf(w0, d, b)); }
        s[t] = v; mx = fmaxf(mx, v);
    }
    #pragma unroll
    for (int o = 16; o; o >>= 1) mx = fmaxf(mx, __shfl_xor_sync(0xffffffffu, mx, o));
    float esum = 0.f;
    #pragma unroll
    for (int t = 0; t < 10; t++) esum += __expf(s[t] - mx);
    #pragma unroll
    for (int o = 16; o; o >>= 1) esum += __shfl_xor_sync(0xffffffffu, esum, o);
    if (lane == 0) {
        float g = 1.0f / (1.0f + __expf(-gating[h]));
        g_posmx[row]  = mx;
        g_posinv[row] = g / esum;
    }
}

// =====================================================================
// GEMM: out[M,Ncols] = A[M,256] @ W[Ncols,256]^T
// 128x128 tile, KT=16 double-buffered, FFMA2; A stored in smem as
// duplicated (a,a) u64 pairs -> inner loop has zero packing MOVs.
// mode 0: A=x, W=[Wqk;Wv], scatter into g_q/g_k/g_v
// mode 1: A=g_oh, W=Wproj, out = val + bias
// =====================================================================
#define KT 16
#define GEMM_SMEM (2*KT*128*8 + 2*KT*132*4)   // As2 + Bs = 49664 B

__global__ __launch_bounds__(256, 2)
void gemm_kernel(const float* __restrict__ A,
                 const float* __restrict__ W0,
                 const float* __restrict__ W1,
                 const float* __restrict__ bias,
                 float* __restrict__ out,
                 int mode)
{
    extern __shared__ __align__(16) char gsm[];
    // As2[buf][k][row] : dup pairs
    unsigned long long* As2 = (unsigned long long*)gsm;            // 2*KT*128 u64
    float* Bs = (float*)(gsm + 2*KT*128*8);                        // 2*[KT][132]

    int tid  = threadIdx.x;
    int row0 = blockIdx.y * 128;
    int col0 = blockIdx.x * 128;
    int tx = tid & 15, ty = tid >> 4;

    const float* Ap = (mode == 0) ? A : g_oh;

    int lr = tid >> 1;
    int lk = (tid & 1) * 8;
    const float* arow = Ap + (size_t)(row0 + lr) * 256 + lk;
    int c = col0 + lr;
    const float* wrow;
    if (mode == 0) wrow = (c < 512) ? (W0 + (size_t)c * 256 + lk)
                                    : (W1 + (size_t)(c - 512) * 256 + lk);
    else           wrow = W0 + (size_t)c * 256 + lk;

    unsigned long long acc2[8][4];
    #pragma unroll
    for (int i = 0; i < 8; i++)
        #pragma unroll
        for (int jp = 0; jp < 4; jp++) acc2[i][jp] = 0ULL;

    float4 ra0, ra1, rb0, rb1;
    ra0 = *(const float4*)(arow + 0);
    ra1 = *(const float4*)(arow + 4);
    rb0 = *(const float4*)(wrow + 0);
    rb1 = *(const float4*)(wrow + 4);
    int buf = 0;
    {
        unsigned long long* Ad = As2 + 0;
        float* Bd = Bs + 0;
        Ad[(lk+0)*128+lr]=pk2(ra0.x,ra0.x); Ad[(lk+1)*128+lr]=pk2(ra0.y,ra0.y);
        Ad[(lk+2)*128+lr]=pk2(ra0.z,ra0.z); Ad[(lk+3)*128+lr]=pk2(ra0.w,ra0.w);
        Ad[(lk+4)*128+lr]=pk2(ra1.x,ra1.x); Ad[(lk+5)*128+lr]=pk2(ra1.y,ra1.y);
        Ad[(lk+6)*128+lr]=pk2(ra1.z,ra1.z); Ad[(lk+7)*128+lr]=pk2(ra1.w,ra1.w);
        Bd[(lk+0)*132+lr]=rb0.x; Bd[(lk+1)*132+lr]=rb0.y;
        Bd[(lk+2)*132+lr]=rb0.z; Bd[(lk+3)*132+lr]=rb0.w;
        Bd[(lk+4)*132+lr]=rb1.x; Bd[(lk+5)*132+lr]=rb1.y;
        Bd[(lk+6)*132+lr]=rb1.z; Bd[(lk+7)*132+lr]=rb1.w;
    }
    __syncthreads();

    for (int k0 = 0; k0 < 256; k0 += KT) {
        bool has_next = (k0 + KT) < 256;
        if (has_next) {
            ra0 = *(const float4*)(arow + k0 + KT + 0);
            ra1 = *(const float4*)(arow + k0 + KT + 4);
            rb0 = *(const float4*)(wrow + k0 + KT + 0);
            rb1 = *(const float4*)(wrow + k0 + KT + 4);
        }
        const unsigned long long* Ab = As2 + buf * (KT*128);
        const float* Bb2 = Bs + buf * (KT*132);
        #pragma unroll
        for (int kk = 0; kk < KT; kk++) {
            ulonglong2 a01 = *(const ulonglong2*)&Ab[kk*128 + ty*4];
            ulonglong2 a23 = *(const ulonglong2*)&Ab[kk*128 + ty*4 + 2];
            ulonglong2 a45 = *(const ulonglong2*)&Ab[kk*128 + 64 + ty*4];
            ulonglong2 a67 = *(const ulonglong2*)&Ab[kk*128 + 64 + ty*4 + 2];
            ulonglong2 bb0 = *(const ulonglong2*)&Bb2[kk*132 + tx*4];
            ulonglong2 bb1 = *(const ulonglong2*)&Bb2[kk*132 + 64 + tx*4];
            unsigned long long ap[8] = {a01.x, a01.y, a23.x, a23.y,
                                        a45.x, a45.y, a67.x, a67.y};
            unsigned long long bp[4] = {bb0.x, bb0.y, bb1.x, bb1.y};
            #pragma unroll
            for (int i = 0; i < 8; i++)
                #pragma unroll
                for (int jp = 0; jp < 4; jp++)
                    fma2(acc2[i][jp], ap[i], bp[jp]);
        }
        if (has_next) {
            int nb = buf ^ 1;
            unsigned long long* Ad = As2 + nb * (KT*128);
            float* Bd = Bs + nb * (KT*132);
            Ad[(lk+0)*128+lr]=pk2(ra0.x,ra0.x); Ad[(lk+1)*128+lr]=pk2(ra0.y,ra0.y);
            Ad[(lk+2)*128+lr]=pk2(ra0.z,ra0.z); Ad[(lk+3)*128+lr]=pk2(ra0.w,ra0.w);
            Ad[(lk+4)*128+lr]=pk2(ra1.x,ra1.x); Ad[(lk+5)*128+lr]=pk2(ra1.y,ra1.y);
            Ad[(lk+6)*128+lr]=pk2(ra1.z,ra1.z); Ad[(lk+7)*128+lr]=pk2(ra1.w,ra1.w);
            Bd[(lk+0)*132+lr]=rb0.x; Bd[(lk+1)*132+lr]=rb0.y;
            Bd[(lk+2)*132+lr]=rb0.z; Bd[(lk+3)*132+lr]=rb0.w;
            Bd[(lk+4)*132+lr]=rb1.x; Bd[(lk+5)*132+lr]=rb1.y;
            Bd[(lk+6)*132+lr]=rb1.z; Bd[(lk+7)*132+lr]=rb1.w;
            __syncthreads();
            buf = nb;
        }
    }

    #pragma unroll
    for (int i = 0; i < 8; i++) {
        int r = row0 + ((i < 4) ? (ty*4 + i) : (64 + ty*4 + i - 4));
        int bidx = r / Nn, n = r % Nn;
        #pragma unroll
        for (int jp = 0; jp < 4; jp++) {
            int col = col0 + ((jp < 2) ? (tx*4 + jp*2) : (64 + tx*4 + (jp-2)*2));
            float d0, d1; upk2(d0, d1, acc2[i][jp]);
            if (mode == 0) {
                int d = col & 31;
                if (col < 512) {
                    int h = (col >> 5) & 7;
                    float* dst = (col < 256) ? g_q : g_k;
                    *(float2*)(dst + (((size_t)bidx*Hh + h)*Nn + n)*HD + d) = make_float2(d0, d1);
                } else {
                    int h = (col - 512) >> 5;
                    *(float2*)(g_v + (((size_t)bidx*Hh + h)*Nn + n)*HD + d) = make_float2(d0, d1);
                }
            } else {
                *(float2*)(out + (size_t)r * 256 + col) =
                    make_float2(d0 + bias[col], d1 + bias[col + 1]);
            }
        }
    }
}

// =====================================================================
// Attention: one CTA per (b,h), 8 warps, QR=4, 2 CTAs/SM.
// No big attn-row buffer: AV restructured into 32-m blocks; scores for a
// block transpose through a 512B/warp sc tile; pos-mix fused at block
// write; AV accumulates m-paired FFMA2 against pre-paired V.
// attn = (1-g)*softmax(QK^T*scale) + g*pos  (rows sum to 1 -> no renorm)
// =====================================================================
#define SM_U64_VS2 ((Nn/2)*32)                 // 4800 u64
#define SM_F_KS    (Nn*KP)                     // 9900 f
#define ATTN_SMEM_BYTES (SM_U64_VS2*8 + (SM_F_KS + AW*32*QR + AW*QR*32)*4)

__global__ __launch_bounds__(AW*32, 2)
void attn_kernel(const float* __restrict__ Wpos,
                 const float* __restrict__ bpos,
                 const float* __restrict__ gating)
{
    extern __shared__ __align__(16) unsigned long long smu[];
    unsigned long long* vs2 = smu;                         // [(m/2)*32+d] = (V[m],V[m+1])
    float* ks  = (float*)(smu + SM_U64_VS2);               // [m*KP + d]
    float* qs  = ks + SM_F_KS;                             // [wid][d*QR+qq]
    float* scb = qs + AW*32*QR;                            // [wid][qq*32+j]

    int bh = blockIdx.x;               // b*8 + h
    int h  = bh & 7, bidx = bh >> 3;
    int tid = threadIdx.x, wid = tid >> 5, lane = tid & 31;

    const float* kg = g_k + (size_t)bh * Nn * HD;
    const float* vg = g_v + (size_t)bh * Nn * HD;
    const float* qg = g_q + (size_t)bh * Nn * HD;

    // stage K (pitch 33, scalar conflict-free)
    for (int i = tid; i < Nn * 8; i += AW*32) {
        int m = i >> 3, d = (i & 7) * 4;
        float4 kv4 = *(const float4*)(kg + m*HD + d);
        ks[m*KP + d + 0] = kv4.x; ks[m*KP + d + 1] = kv4.y;
        ks[m*KP + d + 2] = kv4.z; ks[m*KP + d + 3] = kv4.w;
    }
    // stage V paired over adjacent m
    for (int i = tid; i < (Nn/2) * 8; i += AW*32) {
        int mp = i >> 3, d = (i & 7) * 4;
        float4 va = *(const float4*)(vg + (2*mp)*HD + d);
        float4 vb = *(const float4*)(vg + (2*mp+1)*HD + d);
        vs2[mp*32 + d + 0] = pk2(va.x, vb.x);
        vs2[mp*32 + d + 1] = pk2(va.y, vb.y);
        vs2[mp*32 + d + 2] = pk2(va.z, vb.z);
        vs2[mp*32 + d + 3] = pk2(va.w, vb.w);
    }
    __syncthreads();

    float g  = 1.0f / (1.0f + __expf(-gating[h]));
    float w0 = Wpos[h*3+0], w2 = Wpos[h*3+2], bps = bpos[h];
    const float scale = 0.17677669529663687f;   // 1/sqrt(32)
    float* myq  = qs  + wid * (32*QR);
    float* mysc = scb + wid * (QR*32);

    // n0 = wid*4 + 32*pass; max n0 = 296 -> all 4 queries always valid
    for (int n0 = wid*QR; n0 < Nn; n0 += AW*QR) {
        // stage q interleaved myq[d*QR+qq] via one STS.128 (lane = d)
        {
            float q0 = qg[(n0+0)*HD + lane];
            float q1 = qg[(n0+1)*HD + lane];
            float q2 = qg[(n0+2)*HD + lane];
            float q3 = qg[(n0+3)*HD + lane];
            *(float4*)&myq[lane*QR] = make_float4(q0, q1, q2, q3);
        }
        __syncwarp();

        // ---- QK: acc2[p][t] = {score(2p), score(2p+1)} at m=t*32+lane ----
        unsigned long long acc2[2][10];
        #pragma unroll
        for (int p = 0; p < 2; p++)
            #pragma unroll
            for (int t = 0; t < 10; t++) acc2[p][t] = 0ULL;

        #pragma unroll
        for (int d = 0; d < HD; d++) {
            ulonglong2 qp = *(const ulonglong2*)&myq[d*QR];   // (q0,q1),(q2,q3)
            #pragma unroll
            for (int t = 0; t < 10; t++) {
                float kv = ks[(t*32 + lane)*KP + d];
                unsigned long long kp = pk2(kv, kv);
                fma2(acc2[0][t], qp.x, kp);
                fma2(acc2[1][t], qp.y, kp);
            }
        }

        // ---- softmax stats per query (keep exp values in regs) ----
        float s[QR][10], inv[QR], pmx[QR], pw[QR];
        #pragma unroll
        for (int qq = 0; qq < QR; qq++) {
            int n = n0 + qq;
            float mx = -1e30f;
            #pragma unroll
            for (int t = 0; t < 10; t++) {
                float lo, hi; upk2(lo, hi, acc2[qq >> 1][t]);
                float v = (qq & 1) ? hi : lo;
                int m = t*32 + lane;
                v = (m < Nn) ? v * scale : -1e30f;
                s[qq][t] = v; mx = fmaxf(mx, v);
            }
            #pragma unroll
            for (int o = 16; o; o >>= 1) mx = fmaxf(mx, __shfl_xor_sync(0xffffffffu, mx, o));
            float esum = 0.f;
            #pragma unroll
            for (int t = 0; t < 10; t++) { s[qq][t] = __expf(s[qq][t] - mx); esum += s[qq][t]; }
            #pragma unroll
            for (int o = 16; o; o >>= 1) esum += __shfl_xor_sync(0xffffffffu, esum, o);
            inv[qq] = (1.0f - g) / esum;
            pmx[qq] = g_posmx[h*Nn + n];
            pw[qq]  = g_posinv[h*Nn + n];
        }

        // ---- AV in 32-m blocks through per-warp sc tile ----
        unsigned long long o2[QR];
        #pragma unroll
        for (int qq = 0; qq < QR; qq++) o2[qq] = 0ULL;

        #pragma unroll
        for (int t = 0; t < 10; t++) {
            int m = t*32 + lane;
            float fm = (float)m;
            #pragma unroll
            for (int qq = 0; qq < QR; qq++) {
                float av = 0.f;
                if (m < Nn) {
                    float dd = fm - (float)(n0 + qq);
                    float pe = __expf(fmaf(w2*dd, dd, fmaf(w0, dd, bps)) - pmx[qq]) * pw[qq];
                    av = fmaf(s[qq][t], inv[qq], pe);
                }
                mysc[qq*32 + lane] = av;
            }
            __syncwarp();
            int jpmax = (t < 9) ? 16 : 6;      // block 9 covers m=288..299
            for (int jp = 0; jp < jpmax; jp++) {
                unsigned long long vp = vs2[(t*16 + jp)*32 + lane];
                #pragma unroll
                for (int qq = 0; qq < QR; qq++) {
                    unsigned long long a2 = *(const unsigned long long*)&mysc[qq*32 + jp*2];
                    fma2(o2[qq], a2, vp);
                }
            }
            __syncwarp();
        }

        #pragma unroll
        for (int qq = 0; qq < QR; qq++) {
            float lo, hi; upk2(lo, hi, o2[qq]);
            g_oh[((size_t)bidx*Nn + (n0+qq))*Cc + h*HD + lane] = lo + hi;
        }
    }
}

// =====================================================================
extern "C" void kernel_launch(void* const* d_in, const int* in_sizes, int n_in,
                              void* d_out, int out_size)
{
    const float* x      = (const float*)d_in[0];
    const float* Wqk    = (const float*)d_in[1];
    const float* Wv     = (const float*)d_in[2];
    const float* Wpos   = (const float*)d_in[3];
    const float* bpos   = (const float*)d_in[4];
    const float* Wproj  = (const float*)d_in[5];
    const float* bproj  = (const float*)d_in[6];
    const float* gating = (const float*)d_in[7];
    float* out = (float*)d_out;

    cudaFuncSetAttribute(attn_kernel, cudaFuncAttributeMaxDynamicSharedMemorySize,
                         ATTN_SMEM_BYTES);
    cudaFuncSetAttribute(gemm_kernel, cudaFuncAttributeMaxDynamicSharedMemorySize,
                         GEMM_SMEM);

    // 1) positional softmax stats
    pos_kernel<<<(Hh*Nn + 3) / 4, 128>>>(Wpos, bpos, gating);

    // 2) QKV projection: [19200,256] @ [768,256]^T
    dim3 g1(6, ROWS / 128);
    gemm_kernel<<<g1, 256, GEMM_SMEM>>>(x, Wqk, Wv, nullptr, nullptr, 0);

    // 3) fused gated attention, one CTA per (b,h)
    attn_kernel<<<BH, AW*32, ATTN_SMEM_BYTES>>>(Wpos, bpos, gating);

    // 4) output projection + bias
    dim3 g2(2, ROWS / 128);
    gemm_kernel<<<g2, 256, GEMM_SMEM>>>(nullptr, Wproj, nullptr, bproj, out, 1);
}

// round 9
// speedup vs baseline: 1.2949x; 1.1129x over previous
#include <cuda_runtime.h>
#include <math.h>
#include <stdint.h>

// ---------------- problem constants ----------------
#define Bb 64
#define Nn 300
#define Cc 256
#define Hh 8
#define HD 32
#define BH (Bb*Hh)          // 512
#define ROWS (Bb*Nn)        // 19200
#define QR 4                // queries per warp (register-blocked)
#define AW 8                // warps in attention CTA (2 CTAs/SM)
#define KP 33               // float pitch for K rows (conflict-free)

// ---------------- scratch (device globals; no runtime alloc) ----------------
__device__ float g_q[BH * Nn * HD];     // [b,h,n,d]
__device__ float g_k[BH * Nn * HD];
__device__ float g_v[BH * Nn * HD];
__device__ float g_posmx[Hh * Nn];      // per-(h,n) positional logit max
__device__ float g_posinv[Hh * Nn];     // g(h) / sum(exp(logit - max))
__device__ float g_oh[ROWS * Cc];       // attention output, [b,n,h*32+d]

// ---------------- packed f32x2 helpers ----------------
__device__ __forceinline__ unsigned long long pk2(float x, float y) {
    unsigned long long r;
    asm("mov.b64 %0, {%1,%2};" : "=l"(r)
        : "r"(__float_as_uint(x)), "r"(__float_as_uint(y)));
    return r;
}
__device__ __forceinline__ void fma2(unsigned long long& d,
                                     unsigned long long a, unsigned long long b) {
    asm("fma.rn.f32x2 %0, %1, %2, %0;" : "+l"(d) : "l"(a), "l"(b));
}
__device__ __forceinline__ void upk2(float& lo, float& hi, unsigned long long v) {
    uint32_t l, h;
    asm("mov.b64 {%0,%1}, %2;" : "=r"(l), "=r"(h) : "l"(v));
    lo = __uint_as_float(l); hi = __uint_as_float(h);
}

// =====================================================================
// positional softmax stats: logit[h][n][m] = w0*d + w2*d^2 + b, d = m-n.
// =====================================================================
__global__ void pos_kernel(const float* __restrict__ Wpos,
                           const float* __restrict__ bpos,
                           const float* __restrict__ gating)
{
    int row  = blockIdx.x * 4 + (threadIdx.x >> 5);   // h*300 + n
    int lane = threadIdx.x & 31;
    if (row >= Hh * Nn) return;
    int h = row / Nn, n = row % Nn;
    float w0 = Wpos[h*3+0], w2 = Wpos[h*3+2], b = bpos[h];

    float s[10], mx = -1e30f;
    #pragma unroll
    for (int t = 0; t < 10; t++) {
        int m = t*32 + lane;
        float v = -1e30f;
        if (m < Nn) { float d = (float)(m - n); v = fmaf(w2*d, d, fmaf(w0, d, b)); }
        s[t] = v; mx = fmaxf(mx, v);
    }
    #pragma unroll
    for (int o = 16; o; o >>= 1) mx = fmaxf(mx, __shfl_xor_sync(0xffffffffu, mx, o));
    float esum = 0.f;
    #pragma unroll
    for (int t = 0; t < 10; t++) esum += __expf(s[t] - mx);
    #pragma unroll
    for (int o = 16; o; o >>= 1) esum += __shfl_xor_sync(0xffffffffu, esum, o);
    if (lane == 0) {
        float g = 1.0f / (1.0f + __expf(-gating[h]));
        g_posmx[row]  = mx;
        g_posinv[row] = g / esum;
    }
}

// =====================================================================
// GEMM (R6 version — measured 53us proj): out = A[M,256] @ W[N,256]^T
// 128x128 tile, KT=16 double-buffered smem, 8x8/thr, FFMA2 col-pairs.
// mode 0: A=x, W=[Wqk;Wv], scatter into g_q/g_k/g_v
// mode 1: A=g_oh, W=Wproj, out = val + bias
// =====================================================================
#define KT 16
__global__ __launch_bounds__(256, 2)
void gemm_kernel(const float* __restrict__ A,
                 const float* __restrict__ W0,
                 const float* __restrict__ W1,
                 const float* __restrict__ bias,
                 float* __restrict__ out,
                 int mode)
{
    __shared__ __align__(16) float As[2][KT][132];
    __shared__ __align__(16) float Bs[2][KT][132];

    int tid  = threadIdx.x;
    int row0 = blockIdx.y * 128;
    int col0 = blockIdx.x * 128;
    int tx = tid & 15, ty = tid >> 4;

    const float* Ap = (mode == 0) ? A : g_oh;

    int lr = tid >> 1;
    int lk = (tid & 1) * 8;
    const float* arow = Ap + (size_t)(row0 + lr) * 256 + lk;
    int c = col0 + lr;
    const float* wrow;
    if (mode == 0) wrow = (c < 512) ? (W0 + (size_t)c * 256 + lk)
                                    : (W1 + (size_t)(c - 512) * 256 + lk);
    else           wrow = W0 + (size_t)c * 256 + lk;

    unsigned long long acc2[8][4];
    #pragma unroll
    for (int i = 0; i < 8; i++)
        #pragma unroll
        for (int jp = 0; jp < 4; jp++) acc2[i][jp] = 0ULL;

    float4 ra0, ra1, rb0, rb1;
    ra0 = *(const float4*)(arow + 0);
    ra1 = *(const float4*)(arow + 4);
    rb0 = *(const float4*)(wrow + 0);
    rb1 = *(const float4*)(wrow + 4);
    int buf = 0;
    {
        As[0][lk+0][lr]=ra0.x; As[0][lk+1][lr]=ra0.y; As[0][lk+2][lr]=ra0.z; As[0][lk+3][lr]=ra0.w;
        As[0][lk+4][lr]=ra1.x; As[0][lk+5][lr]=ra1.y; As[0][lk+6][lr]=ra1.z; As[0][lk+7][lr]=ra1.w;
        Bs[0][lk+0][lr]=rb0.x; Bs[0][lk+1][lr]=rb0.y; Bs[0][lk+2][lr]=rb0.z; Bs[0][lk+3][lr]=rb0.w;
        Bs[0][lk+4][lr]=rb1.x; Bs[0][lk+5][lr]=rb1.y; Bs[0][lk+6][lr]=rb1.z; Bs[0][lk+7][lr]=rb1.w;
    }
    __syncthreads();

    for (int k0 = 0; k0 < 256; k0 += KT) {
        bool has_next = (k0 + KT) < 256;
        if (has_next) {
            ra0 = *(const float4*)(arow + k0 + KT + 0);
            ra1 = *(const float4*)(arow + k0 + KT + 4);
            rb0 = *(const float4*)(wrow + k0 + KT + 0);
            rb1 = *(const float4*)(wrow + k0 + KT + 4);
        }
        #pragma unroll
        for (int kk = 0; kk < KT; kk++) {
            float4 a0 = *(const float4*)&As[buf][kk][ty*4];
            float4 a1 = *(const float4*)&As[buf][kk][64 + ty*4];
            ulonglong2 bb0 = *(const ulonglong2*)&Bs[buf][kk][tx*4];
            ulonglong2 bb1 = *(const ulonglong2*)&Bs[buf][kk][64 + tx*4];
            unsigned long long bp[4] = {bb0.x, bb0.y, bb1.x, bb1.y};
            float a[8] = {a0.x,a0.y,a0.z,a0.w, a1.x,a1.y,a1.z,a1.w};
            #pragma unroll
            for (int i = 0; i < 8; i++) {
                unsigned long long ap = pk2(a[i], a[i]);
                #pragma unroll
                for (int jp = 0; jp < 4; jp++)
                    fma2(acc2[i][jp], ap, bp[jp]);
            }
        }
        if (has_next) {
            int nb = buf ^ 1;
            As[nb][lk+0][lr]=ra0.x; As[nb][lk+1][lr]=ra0.y; As[nb][lk+2][lr]=ra0.z; As[nb][lk+3][lr]=ra0.w;
            As[nb][lk+4][lr]=ra1.x; As[nb][lk+5][lr]=ra1.y; As[nb][lk+6][lr]=ra1.z; As[nb][lk+7][lr]=ra1.w;
            Bs[nb][lk+0][lr]=rb0.x; Bs[nb][lk+1][lr]=rb0.y; Bs[nb][lk+2][lr]=rb0.z; Bs[nb][lk+3][lr]=rb0.w;
            Bs[nb][lk+4][lr]=rb1.x; Bs[nb][lk+5][lr]=rb1.y; Bs[nb][lk+6][lr]=rb1.z; Bs[nb][lk+7][lr]=rb1.w;
            __syncthreads();
            buf = nb;
        }
    }

    #pragma unroll
    for (int i = 0; i < 8; i++) {
        int r = row0 + ((i < 4) ? (ty*4 + i) : (64 + ty*4 + i - 4));
        int bidx = r / Nn, n = r % Nn;
        #pragma unroll
        for (int jp = 0; jp < 4; jp++) {
            int col = col0 + ((jp < 2) ? (tx*4 + jp*2) : (64 + tx*4 + (jp-2)*2));
            float d0, d1; upk2(d0, d1, acc2[i][jp]);
            if (mode == 0) {
                int d = col & 31;
                if (col < 512) {
                    int h = (col >> 5) & 7;
                    float* dst = (col < 256) ? g_q : g_k;
                    *(float2*)(dst + (((size_t)bidx*Hh + h)*Nn + n)*HD + d) = make_float2(d0, d1);
                } else {
                    int h = (col - 512) >> 5;
                    *(float2*)(g_v + (((size_t)bidx*Hh + h)*Nn + n)*HD + d) = make_float2(d0, d1);
                }
            } else {
                *(float2*)(out + (size_t)r * 256 + col) =
                    make_float2(d0 + bias[col], d1 + bias[col + 1]);
            }
        }
    }
}

// =====================================================================
// Attention: one CTA per (b,h), 8 warps, QR=4, 2 CTAs/SM.
// AV in 32-m blocks through 512B/warp sc tile; score broadcasts fetched
// as LDS.128 quads (4 m per fetch). Pos-mix fused at block write.
// attn = (1-g)*softmax(QK^T*scale) + g*pos  (rows sum to 1 -> no renorm)
// =====================================================================
#define SM_U64_VS2 ((Nn/2)*32)                 // 4800 u64
#define SM_F_KS    (Nn*KP)                     // 9900 f
#define ATTN_SMEM_BYTES (SM_U64_VS2*8 + (SM_F_KS + AW*32*QR + AW*QR*32)*4)

__global__ __launch_bounds__(AW*32, 2)
void attn_kernel(const float* __restrict__ Wpos,
                 const float* __restrict__ bpos,
                 const float* __restrict__ gating)
{
    extern __shared__ __align__(16) unsigned long long smu[];
    unsigned long long* vs2 = smu;                         // [(m/2)*32+d] = (V[m],V[m+1])
    float* ks  = (float*)(smu + SM_U64_VS2);               // [m*KP + d]
    float* qs  = ks + SM_F_KS;                             // [wid][d*QR+qq]
    float* scb = qs + AW*32*QR;                            // [wid][qq*32+j]

    int bh = blockIdx.x;               // b*8 + h
    int h  = bh & 7, bidx = bh >> 3;
    int tid = threadIdx.x, wid = tid >> 5, lane = tid & 31;

    const float* kg = g_k + (size_t)bh * Nn * HD;
    const float* vg = g_v + (size_t)bh * Nn * HD;
    const float* qg = g_q + (size_t)bh * Nn * HD;

    // stage K (pitch 33, scalar conflict-free)
    for (int i = tid; i < Nn * 8; i += AW*32) {
        int m = i >> 3, d = (i & 7) * 4;
        float4 kv4 = *(const float4*)(kg + m*HD + d);
        ks[m*KP + d + 0] = kv4.x; ks[m*KP + d + 1] = kv4.y;
        ks[m*KP + d + 2] = kv4.z; ks[m*KP + d + 3] = kv4.w;
    }
    // stage V paired over adjacent m
    for (int i = tid; i < (Nn/2) * 8; i += AW*32) {
        int mp = i >> 3, d = (i & 7) * 4;
        float4 va = *(const float4*)(vg + (2*mp)*HD + d);
        float4 vb = *(const float4*)(vg + (2*mp+1)*HD + d);
        vs2[mp*32 + d + 0] = pk2(va.x, vb.x);
        vs2[mp*32 + d + 1] = pk2(va.y, vb.y);
        vs2[mp*32 + d + 2] = pk2(va.z, vb.z);
        vs2[mp*32 + d + 3] = pk2(va.w, vb.w);
    }
    __syncthreads();

    float g  = 1.0f / (1.0f + __expf(-gating[h]));
    float w0 = Wpos[h*3+0], w2 = Wpos[h*3+2], bps = bpos[h];
    const float scale = 0.17677669529663687f;   // 1/sqrt(32)
    float* myq  = qs  + wid * (32*QR);
    float* mysc = scb + wid * (QR*32);

    // n0 = wid*4 + 32*pass; max n0 = 296 -> all 4 queries always valid
    for (int n0 = wid*QR; n0 < Nn; n0 += AW*QR) {
        // stage q interleaved myq[d*QR+qq] via one STS.128 (lane = d)
        {
            float q0 = qg[(n0+0)*HD + lane];
            float q1 = qg[(n0+1)*HD + lane];
            float q2 = qg[(n0+2)*HD + lane];
            float q3 = qg[(n0+3)*HD + lane];
            *(float4*)&myq[lane*QR] = make_float4(q0, q1, q2, q3);
        }
        __syncwarp();

        // ---- QK: acc2[p][t] = {score(2p), score(2p+1)} at m=t*32+lane ----
        unsigned long long acc2[2][10];
        #pragma unroll
        for (int p = 0; p < 2; p++)
            #pragma unroll
            for (int t = 0; t < 10; t++) acc2[p][t] = 0ULL;

        #pragma unroll
        for (int d = 0; d < HD; d++) {
            ulonglong2 qp = *(const ulonglong2*)&myq[d*QR];   // (q0,q1),(q2,q3)
            #pragma unroll
            for (int t = 0; t < 10; t++) {
                float kv = ks[(t*32 + lane)*KP + d];
                unsigned long long kp = pk2(kv, kv);
                fma2(acc2[0][t], qp.x, kp);
                fma2(acc2[1][t], qp.y, kp);
            }
        }

        // ---- softmax stats per query (keep exp values in regs) ----
        float s[QR][10], inv[QR], pmx[QR], pw[QR];
        #pragma unroll
        for (int qq = 0; qq < QR; qq++) {
            int n = n0 + qq;
            float mx = -1e30f;
            #pragma unroll
            for (int t = 0; t < 10; t++) {
                float lo, hi; upk2(lo, hi, acc2[qq >> 1][t]);
                float v = (qq & 1) ? hi : lo;
                int m = t*32 + lane;
                v = (m < Nn) ? v * scale : -1e30f;
                s[qq][t] = v; mx = fmaxf(mx, v);
            }
            #pragma unroll
            for (int o = 16; o; o >>= 1) mx = fmaxf(mx, __shfl_xor_sync(0xffffffffu, mx, o));
            float esum = 0.f;
            #pragma unroll
            for (int t = 0; t < 10; t++) { s[qq][t] = __expf(s[qq][t] - mx); esum += s[qq][t]; }
            #pragma unroll
            for (int o = 16; o; o >>= 1) esum += __shfl_xor_sync(0xffffffffu, esum, o);
            inv[qq] = (1.0f - g) / esum;
            pmx[qq] = g_posmx[h*Nn + n];
            pw[qq]  = g_posinv[h*Nn + n];
        }

        // ---- AV in 32-m blocks through per-warp sc tile ----
        unsigned long long o2[QR];
        #pragma unroll
        for (int qq = 0; qq < QR; qq++) o2[qq] = 0ULL;

        #pragma unroll
        for (int t = 0; t < 10; t++) {
            int m = t*32 + lane;
            float fm = (float)m;
            #pragma unroll
            for (int qq = 0; qq < QR; qq++) {
                float av = 0.f;
                if (m < Nn) {
                    float dd = fm - (float)(n0 + qq);
                    float pe = __expf(fmaf(w2*dd, dd, fmaf(w0, dd, bps)) - pmx[qq]) * pw[qq];
                    av = fmaf(s[qq][t], inv[qq], pe);
                }
                mysc[qq*32 + lane] = av;
            }
            __syncwarp();
            // 4 m per iteration: 2 paired-V loads + 1 LDS.128 quad broadcast/query
            int j4max = (t < 9) ? 8 : 3;       // block 9 covers m=288..299 (12 m)
            for (int j4 = 0; j4 < j4max; j4++) {
                unsigned long long vp0 = vs2[(t*16 + 2*j4 + 0)*32 + lane];
                unsigned long long vp1 = vs2[(t*16 + 2*j4 + 1)*32 + lane];
                #pragma unroll
                for (int qq = 0; qq < QR; qq++) {
                    ulonglong2 a4 = *(const ulonglong2*)&mysc[qq*32 + j4*4];
                    fma2(o2[qq], a4.x, vp0);
                    fma2(o2[qq], a4.y, vp1);
                }
            }
            __syncwarp();
        }

        #pragma unroll
        for (int qq = 0; qq < QR; qq++) {
            float lo, hi; upk2(lo, hi, o2[qq]);
            g_oh[((size_t)bidx*Nn + (n0+qq))*Cc + h*HD + lane] = lo + hi;
        }
    }
}

// =====================================================================
extern "C" void kernel_launch(void* const* d_in, const int* in_sizes, int n_in,
                              void* d_out, int out_size)
{
    const float* x      = (const float*)d_in[0];
    const float* Wqk    = (const float*)d_in[1];
    const float* Wv     = (const float*)d_in[2];
    const float* Wpos   = (const float*)d_in[3];
    const float* bpos   = (const float*)d_in[4];
    const float* Wproj  = (const float*)d_in[5];
    const float* bproj  = (const float*)d_in[6];
    const float* gating = (const float*)d_in[7];
    float* out = (float*)d_out;

    cudaFuncSetAttribute(attn_kernel, cudaFuncAttributeMaxDynamicSharedMemorySize,
                         ATTN_SMEM_BYTES);

    // 1) positional softmax stats
    pos_kernel<<<(Hh*Nn + 3) / 4, 128>>>(Wpos, bpos, gating);

    // 2) QKV projection: [19200,256] @ [768,256]^T
    dim3 g1(6, ROWS / 128);
    gemm_kernel<<<g1, 256>>>(x, Wqk, Wv, nullptr, nullptr, 0);

    // 3) fused gated attention, one CTA per (b,h)
    attn_kernel<<<BH, AW*32, ATTN_SMEM_BYTES>>>(Wpos, bpos, gating);

    // 4) output projection + bias
    dim3 g2(2, ROWS / 128);
    gemm_kernel<<<g2, 256>>>(nullptr, Wproj, nullptr, bproj, out, 1);
}